// round 16
// baseline (speedup 1.0000x reference)
#include <cuda_runtime.h>
#include <cstdint>
#include <math.h>

#define BATCH 8192
#define TDIM 64
#define FDIM 64
#define CWIN 20
#define WWIN 30
#define EF   64
#define BEGIN 15
#define ROWS 49                 // C + W - 1
#define OUT_ROW (5*EF)          // 320
#define OUT_STRIDE (WWIN*OUT_ROW) // 9600 floats per batch
#define NCOLS (WWIN*EF)         // 1920

#define NPFX 2048
#define NBINS 10240
#define NBINS_TOT 10272         // padded, /4 for uint4

// Scratch: keys transposed [col][b] (60MB), u16 ranks (30MB),
// per-column global histograms (79MB, L2-resident during rank).
__device__ unsigned int   g_xT[(size_t)NCOLS * BATCH];
__device__ unsigned short g_rank16[(size_t)NCOLS * BATCH];
__device__ unsigned int   g_hist[(size_t)NCOLS * NBINS_TOT];
__device__ unsigned int   g_lut[NPFX];

// ---------------------------------------------------------------------------
// Kernel 0: transpose + key conversion. xT[w*64+e][b] = ord(-x[b][34+w][e]).
// ---------------------------------------------------------------------------
__global__ __launch_bounds__(256) void transpose_kernel(const float* __restrict__ x) {
    __shared__ unsigned int tile[32 * 65];
    const int bbase = blockIdx.x * 32;
    const int w = blockIdx.y;
    const int row = BEGIN + w + (CWIN - 1);   // 34 + w
    const int t = threadIdx.x;

    #pragma unroll
    for (int i = 0; i < 8; i++) {
        const int j = t + i * 256;
        const int b0 = j >> 6, e = j & 63;
        float v = __ldg(&x[(size_t)(bbase + b0) * (TDIM * FDIM) + row * FDIM + e]);
        unsigned int f = __float_as_uint(-v);
        tile[b0 * 65 + e] = (f & 0x80000000u) ? ~f : (f | 0x80000000u);
    }
    __syncthreads();
    #pragma unroll
    for (int i = 0; i < 8; i++) {
        const int j = t + i * 256;
        const int e = j >> 5, b0 = j & 31;
        g_xT[(size_t)(w * EF + e) * BATCH + bbase + b0] = tile[b0 * 65 + e];
    }
}

// ---------------------------------------------------------------------------
// Kernel 1: per-batch window stats (proven 256-thr form; ~10K regs,
// 12.5KB smem -> up to 3 CTAs co-reside beside one rank CTA).
// ---------------------------------------------------------------------------
__global__ __launch_bounds__(256) void stats_kernel(const float* __restrict__ x,
                                                    float* __restrict__ out) {
    __shared__ float s[ROWS * FDIM];
    const int b = blockIdx.x;
    const float* xb = x + (size_t)b * TDIM * FDIM + BEGIN * FDIM;

    const float4* src4 = (const float4*)xb;
    float4* s4 = (float4*)s;
    for (int i = threadIdx.x; i < ROWS * FDIM / 4; i += 256) s4[i] = src4[i];
    __syncthreads();

    float* outb = out + (size_t)b * OUT_STRIDE;
    for (int item = threadIdx.x; item < WWIN * EF; item += 256) {
        const int w = item >> 6;
        const int e = item & 63;
        const float* p = s + w * FDIM + e;

        float v0 = p[0];
        float sum = v0, mx = v0, mn = v0;
        #pragma unroll
        for (int c = 1; c < CWIN; c++) {
            float v = p[c * FDIM];
            sum += v;
            mx = fmaxf(mx, v);
            mn = fminf(mn, v);
        }
        const float mean = sum * (1.0f / CWIN);
        float var = 0.0f;
        #pragma unroll
        for (int c = 0; c < CWIN; c++) {
            float d = p[c * FDIM] - mean;
            var += d * d;
        }
        const float sd = sqrtf(var * (1.0f / (CWIN - 1)));

        float* o = outb + w * OUT_ROW + e;
        o[0]      = mean;
        o[EF]     = sd;
        o[3 * EF] = mx;
        o[4 * EF] = mn;
    }
}

// ---------------------------------------------------------------------------
// Equalized monotone binning LUT (11-bit prefix). Entry = (base << 4) | e.
// ---------------------------------------------------------------------------
__global__ __launch_bounds__(1024) void lut_init_kernel() {
    __shared__ unsigned int cap[NPFX];
    __shared__ unsigned int tsum[1024];
    __shared__ unsigned int wsum[32];
    const int t = threadIdx.x;

    #pragma unroll
    for (int k = 0; k < 2; k++) {
        const int p = t * 2 + k;
        auto o2v = [](unsigned int o) -> float {
            unsigned int f = (o & 0x80000000u) ? (o & 0x7FFFFFFFu) : ~o;
            return -__uint_as_float(f);
        };
        float v_a = o2v((unsigned int)p << 21);
        float v_b = o2v((unsigned int)(p + 1) << 21);
        float phi_a = 0.5f * (1.0f + erff(v_a * 0.70710678f));
        float phi_b = 0.5f * (1.0f + erff(v_b * 0.70710678f));
        float mass = phi_a - phi_b;
        int e = 0;
        if (mass > 0.0f && isfinite(mass)) {
            float le = log2f(mass * 8192.0f);
            e = (int)floorf(le);
            if (e < 0) e = 0;
            if (e > 12) e = 12;
        }
        cap[p] = 1u << e;
    }
    __syncthreads();

    unsigned int s0 = cap[t * 2] + cap[t * 2 + 1];
    const int lane = t & 31, wid = t >> 5;
    unsigned int inc = s0;
    #pragma unroll
    for (int d = 1; d < 32; d <<= 1) {
        unsigned int n = __shfl_up_sync(0xffffffffu, inc, d);
        if (lane >= d) inc += n;
    }
    if (lane == 31) wsum[wid] = inc;
    __syncthreads();
    if (wid == 0) {
        unsigned int v = wsum[lane];
        unsigned int wi = v;
        #pragma unroll
        for (int d = 1; d < 32; d <<= 1) {
            unsigned int n = __shfl_up_sync(0xffffffffu, wi, d);
            if (lane >= d) wi += n;
        }
        wsum[lane] = wi - v;
    }
    __syncthreads();
    tsum[t] = (inc - s0) + wsum[wid];
    __syncthreads();

    unsigned int base = tsum[t];
    #pragma unroll
    for (int k = 0; k < 2; k++) {
        const int p = t * 2 + k;
        unsigned int c = cap[p];
        unsigned int e = 31 - __clz(c);
        g_lut[p] = (base << 4) | e;
        base += c;
    }
}

// ---------------------------------------------------------------------------
// Kernel 2: exact descending rank per (w,e) column -> u16 to g_rank16.
// Histogram atomics moved to L2 (ATOMG spread ~1.29 cyc/lane vs ATOMS 2),
// offloading the smem/LSU port. Then copy slice->smem, scan, scatter
// base+off (no atomics), tiny-bin walk.
// ---------------------------------------------------------------------------
#define RT 512
#define ELPT 16
#define HPAD 32
#define DYN_SMEM ((NBINS+HPAD)*4 + BATCH*4 + BATCH*2 + NPFX*4)  // 98432

__global__ __launch_bounds__(RT) void rank_kernel() {
    extern __shared__ unsigned char dyn[];
    unsigned int*   hist = (unsigned int*)dyn;                                   // 40.1 KB
    unsigned int*   S    = (unsigned int*)(dyn + (NBINS+HPAD)*4);                // 32 KB
    unsigned short* A    = (unsigned short*)(dyn + (NBINS+HPAD)*4 + BATCH*4);    // 16 KB
    unsigned int*   lut  = (unsigned int*)(dyn + (NBINS+HPAD)*4 + BATCH*4 + BATCH*2); // 8 KB
    __shared__ unsigned int warpSums[32];

    const int col = blockIdx.x;          // w*64 + e
    const int t = threadIdx.x;
    const int lane = t & 31;
    const int wid  = t >> 5;             // 0..15

    unsigned int* ghist = g_hist + (size_t)col * NBINS_TOT;

    // zero this column's global hist slice (L2 write-allocate, stays resident)
    {
        uint4* gh4 = (uint4*)ghist;
        #pragma unroll
        for (int i = 0; i < 6; i++) {
            const int idx = t + i * RT;
            if (idx < NBINS_TOT / 4) gh4[idx] = make_uint4(0, 0, 0, 0);
        }
    }
    #pragma unroll
    for (int i = 0; i < NPFX / RT; i++) lut[t + i * RT] = __ldg(&g_lut[t + i * RT]);

    // coalesced key loads (L2-hot from transpose)
    unsigned int myu[ELPT];
    const unsigned int* xc = g_xT + (size_t)col * BATCH;
    #pragma unroll
    for (int k = 0; k < ELPT; k++) myu[k] = __ldg(&xc[t + k * RT]);
    __syncthreads();    // zeros visible CTA-wide before atomics

    // single L2-atomic pass: bin + within-bin sequence number, packed
    unsigned int packed[ELPT];          // bin (14b) | off<<14 (13b)
    #pragma unroll
    for (int k = 0; k < ELPT; k++) {
        const unsigned int u = myu[k];
        const unsigned int ent = lut[u >> 21];
        const unsigned int eb = ent & 15u;
        const unsigned int bin = (ent >> 4) + ((u >> (21 - eb)) & ((1u << eb) - 1u));
        const unsigned int off = atomicAdd(&ghist[bin], 1u);
        packed[k] = bin | (off << 14);
    }
    __syncthreads();    // every thread holds its off -> ghist slice is final

    // copy counts L2 -> smem (20 independent loads/thread, latency hidden)
    #pragma unroll
    for (int i = 0; i < NBINS / RT; i++) {
        const int idx = t + i * RT;
        hist[idx] = ghist[idx];
    }
    __syncthreads();

    // exclusive scan in smem: 16 warps x 640-bin chunks (20 rounds)
    const int wbase = wid * (NBINS / 16);
    unsigned int carry = 0;
    #pragma unroll
    for (int r = 0; r < NBINS / 16 / 32; r++) {
        unsigned int v = hist[wbase + r * 32 + lane];
        unsigned int inc = v;
        #pragma unroll
        for (int d = 1; d < 32; d <<= 1) {
            unsigned int n = __shfl_up_sync(0xffffffffu, inc, d);
            if (lane >= d) inc += n;
        }
        hist[wbase + r * 32 + lane] = (inc - v) + carry;
        carry += __shfl_sync(0xffffffffu, inc, 31);
    }
    if (lane == 31) warpSums[wid] = carry;
    __syncthreads();
    if (wid == 0) {
        unsigned int orig = (lane < 16) ? warpSums[lane] : 0u;
        unsigned int inc = orig;
        #pragma unroll
        for (int d = 1; d < 32; d <<= 1) {
            unsigned int n = __shfl_up_sync(0xffffffffu, inc, d);
            if (lane >= d) inc += n;
        }
        if (lane < 16) warpSums[lane] = inc - orig;
    }
    __syncthreads();
    {
        const unsigned int add = warpSums[wid];
        if (add) {
            #pragma unroll
            for (int r = 0; r < NBINS / 16 / 32; r++)
                hist[wbase + r * 32 + lane] += add;
        }
    }
    if (t == 0) hist[NBINS] = BATCH;
    __syncthreads();

    // scatter via base + off (no atomics); smem hist stays exclusive-base
    #pragma unroll
    for (int k = 0; k < ELPT; k++) {
        const unsigned int bin = packed[k] & 16383u;
        const unsigned int off = packed[k] >> 14;
        const unsigned int pos = hist[bin] + off;
        S[pos] = myu[k];
        A[pos] = (unsigned short)(t + k * RT);
    }
    __syncthreads();

    // walk near-singleton bins; tie-index load only on key equality (rare)
    unsigned short* rc = g_rank16 + (size_t)col * BATCH;
    #pragma unroll
    for (int k = 0; k < ELPT; k++) {
        const int b = t + k * RT;
        const unsigned int u = myu[k];
        const unsigned int bin = packed[k] & 16383u;
        const unsigned int start = hist[bin];
        const unsigned int end = hist[bin + 1];
        unsigned int cnt = 0;
        for (unsigned int p = start; p < end; p++) {
            const unsigned int u2 = S[p];
            cnt += (u2 < u);
            if (u2 == u) cnt += ((int)A[p] < b);
        }
        rc[b] = (unsigned short)(start + cnt);   // coalesced u16 store
    }
}

// ---------------------------------------------------------------------------
// Kernel 3: transpose ranks back into out (coalesced both sides).
// ---------------------------------------------------------------------------
__global__ __launch_bounds__(256) void rank_out_kernel(float* __restrict__ out) {
    __shared__ unsigned int tile[64 * 33];   // [e][b/2] u16x2, pad 33
    const int b0 = blockIdx.x * 64;
    const int w = blockIdx.y;
    const int t = threadIdx.x;
    const int lane = t & 31;
    const int wr = t >> 5;                   // warp id 0..7

    #pragma unroll
    for (int i = 0; i < 8; i++) {
        const int e = wr * 8 + i;
        const unsigned int* src = (const unsigned int*)
            (g_rank16 + (size_t)(w * EF + e) * BATCH + b0);
        tile[e * 33 + lane] = src[lane];
    }
    __syncthreads();

    const float invB = 1.0f / BATCH;
    #pragma unroll
    for (int i = 0; i < 8; i++) {
        const int b = wr * 8 + i;
        float* o = out + (size_t)(b0 + b) * OUT_STRIDE + w * OUT_ROW + 2 * EF;
        #pragma unroll
        for (int h = 0; h < 2; h++) {
            const int e = h * 32 + lane;
            const unsigned int pk = tile[e * 33 + (b >> 1)];
            const unsigned int r = (b & 1) ? (pk >> 16) : (pk & 0xFFFFu);
            o[e] = (float)r * invB;
        }
    }
}

// ---------------------------------------------------------------------------
// Side stream at LOW priority: rank-path CTAs win dispatch slots, stats
// fills leftover resources (3 stats CTAs fit beside one rank CTA: regs
// 32K + 3*10K < 64K, smem 98 + 3*12.5 < 228).
// ---------------------------------------------------------------------------
struct GpuRes {
    cudaStream_t s2 = 0;
    cudaEvent_t evFork = 0, evJoin = 0;
    bool ok = false;
    GpuRes() {
        int loP = 0, hiP = 0;
        cudaDeviceGetStreamPriorityRange(&loP, &hiP);   // loP = least priority
        ok = (cudaStreamCreateWithPriority(&s2, cudaStreamNonBlocking, loP) == cudaSuccess) &&
             (cudaEventCreateWithFlags(&evFork, cudaEventDisableTiming) == cudaSuccess) &&
             (cudaEventCreateWithFlags(&evJoin, cudaEventDisableTiming) == cudaSuccess);
    }
};
static GpuRes g_res;

extern "C" void kernel_launch(void* const* d_in, const int* in_sizes, int n_in,
                              void* d_out, int out_size) {
    const float* x = (const float*)d_in[0];
    float* out = (float*)d_out;

    cudaFuncSetAttribute(rank_kernel, cudaFuncAttributeMaxDynamicSharedMemorySize,
                         DYN_SMEM);

    if (g_res.ok) {
        cudaEventRecord(g_res.evFork, 0);
        cudaStreamWaitEvent(g_res.s2, g_res.evFork, 0);
        stats_kernel<<<BATCH, 256, 0, g_res.s2>>>(x, out);   // low priority
        cudaEventRecord(g_res.evJoin, g_res.s2);

        lut_init_kernel<<<1, 1024>>>();
        transpose_kernel<<<dim3(BATCH / 32, WWIN), 256>>>(x);
        rank_kernel<<<NCOLS, RT, DYN_SMEM>>>();
        rank_out_kernel<<<dim3(BATCH / 64, WWIN), 256>>>(out);

        cudaStreamWaitEvent(0, g_res.evJoin, 0);
    } else {
        lut_init_kernel<<<1, 1024>>>();
        stats_kernel<<<BATCH, 256>>>(x, out);
        transpose_kernel<<<dim3(BATCH / 32, WWIN), 256>>>(x);
        rank_kernel<<<NCOLS, RT, DYN_SMEM>>>();
        rank_out_kernel<<<dim3(BATCH / 64, WWIN), 256>>>(out);
    }
}

// round 17
// speedup vs baseline: 1.4073x; 1.4073x over previous
#include <cuda_runtime.h>
#include <cstdint>
#include <math.h>

#define BATCH 8192
#define TDIM 64
#define FDIM 64
#define CWIN 20
#define WWIN 30
#define EF   64
#define BEGIN 15
#define ROWS 49                 // C + W - 1
#define OUT_ROW (5*EF)          // 320
#define OUT_STRIDE (WWIN*OUT_ROW) // 9600 floats per batch
#define NCOLS (WWIN*EF)         // 1920

// Scratch: monotone keys transposed to [col][b] (60MB), u16 ranks (30MB).
__device__ unsigned int   g_xT[(size_t)NCOLS * BATCH];
__device__ unsigned short g_rank16[(size_t)NCOLS * BATCH];

// ---------------------------------------------------------------------------
// Kernel 0: transpose + key conversion. xT[w*64+e][b] = ord(-x[b][34+w][e]).
// HBM roofline (~19us).
// ---------------------------------------------------------------------------
__global__ __launch_bounds__(256) void transpose_kernel(const float* __restrict__ x) {
    __shared__ unsigned int tile[32 * 65];
    const int bbase = blockIdx.x * 32;
    const int w = blockIdx.y;
    const int row = BEGIN + w + (CWIN - 1);   // 34 + w
    const int t = threadIdx.x;

    #pragma unroll
    for (int i = 0; i < 8; i++) {
        const int j = t + i * 256;
        const int b0 = j >> 6, e = j & 63;
        float v = __ldg(&x[(size_t)(bbase + b0) * (TDIM * FDIM) + row * FDIM + e]);
        unsigned int f = __float_as_uint(-v);
        tile[b0 * 65 + e] = (f & 0x80000000u) ? ~f : (f | 0x80000000u);
    }
    __syncthreads();
    #pragma unroll
    for (int i = 0; i < 8; i++) {
        const int j = t + i * 256;
        const int e = j >> 5, b0 = j & 31;
        g_xT[(size_t)(w * EF + e) * BATCH + bbase + b0] = tile[b0 * 65 + e];
    }
}

// ---------------------------------------------------------------------------
// Kernel 1: per-batch window stats — ONE-PASS sum/sumsq (halves LDS traffic
// vs the two-pass mean/centered-variance version; cancellation is benign for
// ~N(0,1) data: error ~2e-6 rel, tolerance 1e-3).
// ---------------------------------------------------------------------------
__global__ __launch_bounds__(256) void stats_kernel(const float* __restrict__ x,
                                                    float* __restrict__ out) {
    __shared__ float s[ROWS * FDIM];
    const int b = blockIdx.x;
    const float* xb = x + (size_t)b * TDIM * FDIM + BEGIN * FDIM;

    const float4* src4 = (const float4*)xb;
    float4* s4 = (float4*)s;
    for (int i = threadIdx.x; i < ROWS * FDIM / 4; i += 256) s4[i] = src4[i];
    __syncthreads();

    float* outb = out + (size_t)b * OUT_STRIDE;
    for (int item = threadIdx.x; item < WWIN * EF; item += 256) {
        const int w = item >> 6;
        const int e = item & 63;
        const float* p = s + w * FDIM + e;   // lane==e -> conflict-free LDS

        float v0 = p[0];
        float sum = v0, sumsq = v0 * v0, mx = v0, mn = v0;
        #pragma unroll
        for (int c = 1; c < CWIN; c++) {
            float v = p[c * FDIM];
            sum += v;
            sumsq = fmaf(v, v, sumsq);
            mx = fmaxf(mx, v);
            mn = fminf(mn, v);
        }
        const float mean = sum * (1.0f / CWIN);
        float var = (sumsq - sum * mean) * (1.0f / (CWIN - 1));
        const float sd = sqrtf(fmaxf(var, 0.0f));

        float* o = outb + w * OUT_ROW + e;   // coalesced 128B per field
        o[0]      = mean;
        o[EF]     = sd;
        o[3 * EF] = mx;
        o[4 * EF] = mn;
    }
}

// ---------------------------------------------------------------------------
// Equalized monotone binning LUT (11-bit prefix). Entry = (base << 4) | e:
// prefix owns 2^e bins, sub-bin = next e key bits. Exactly monotone by
// construction; erf only shapes bin sizes (perf), never correctness.
// ---------------------------------------------------------------------------
#define NPFX 2048
#define NBINS 10240
__device__ unsigned int g_lut[NPFX];

__global__ __launch_bounds__(1024) void lut_init_kernel() {
    __shared__ unsigned int cap[NPFX];
    __shared__ unsigned int tsum[1024];
    __shared__ unsigned int wsum[32];
    const int t = threadIdx.x;

    #pragma unroll
    for (int k = 0; k < 2; k++) {
        const int p = t * 2 + k;
        auto o2v = [](unsigned int o) -> float {
            unsigned int f = (o & 0x80000000u) ? (o & 0x7FFFFFFFu) : ~o;
            return -__uint_as_float(f);
        };
        float v_a = o2v((unsigned int)p << 21);
        float v_b = o2v((unsigned int)(p + 1) << 21);
        float phi_a = 0.5f * (1.0f + erff(v_a * 0.70710678f));
        float phi_b = 0.5f * (1.0f + erff(v_b * 0.70710678f));
        float mass = phi_a - phi_b;
        int e = 0;
        if (mass > 0.0f && isfinite(mass)) {
            float le = log2f(mass * 8192.0f);
            e = (int)floorf(le);
            if (e < 0) e = 0;
            if (e > 12) e = 12;
        }
        cap[p] = 1u << e;
    }
    __syncthreads();

    unsigned int s0 = cap[t * 2] + cap[t * 2 + 1];
    const int lane = t & 31, wid = t >> 5;
    unsigned int inc = s0;
    #pragma unroll
    for (int d = 1; d < 32; d <<= 1) {
        unsigned int n = __shfl_up_sync(0xffffffffu, inc, d);
        if (lane >= d) inc += n;
    }
    if (lane == 31) wsum[wid] = inc;
    __syncthreads();
    if (wid == 0) {
        unsigned int v = wsum[lane];
        unsigned int wi = v;
        #pragma unroll
        for (int d = 1; d < 32; d <<= 1) {
            unsigned int n = __shfl_up_sync(0xffffffffu, wi, d);
            if (lane >= d) wi += n;
        }
        wsum[lane] = wi - v;
    }
    __syncthreads();
    tsum[t] = (inc - s0) + wsum[wid];
    __syncthreads();

    unsigned int base = tsum[t];
    #pragma unroll
    for (int k = 0; k < 2; k++) {
        const int p = t * 2 + k;
        unsigned int c = cap[p];
        unsigned int e = 31 - __clz(c);
        g_lut[p] = (base << 4) | e;
        base += c;
    }
}

// ---------------------------------------------------------------------------
// Kernel 2: exact descending rank per (w,e) column -> u16 to g_rank16.
// Proven R13 config: smem ATOMS histogram (structural floor ~2cyc/lane),
// one atomic pass; scan; scatter base+off; tiny-bin walk.
// ---------------------------------------------------------------------------
#define RT 1024
#define HPAD 32
#define DYN_SMEM ((NBINS+HPAD)*4 + BATCH*4 + BATCH*2 + NPFX*4)  // 98432

__global__ __launch_bounds__(RT) void rank_kernel() {
    extern __shared__ unsigned char dyn[];
    unsigned int*   hist = (unsigned int*)dyn;                                   // 40.1 KB
    unsigned int*   S    = (unsigned int*)(dyn + (NBINS+HPAD)*4);                // 32 KB
    unsigned short* A    = (unsigned short*)(dyn + (NBINS+HPAD)*4 + BATCH*4);    // 16 KB
    unsigned int*   lut  = (unsigned int*)(dyn + (NBINS+HPAD)*4 + BATCH*4 + BATCH*2); // 8 KB
    __shared__ unsigned int warpSums[32];

    const int col = blockIdx.x;          // w*64 + e
    const int t = threadIdx.x;
    const int lane = t & 31;
    const int wid  = t >> 5;

    // vectorized hist zero
    {
        uint4* h4 = (uint4*)hist;
        #pragma unroll
        for (int i = 0; i < 3; i++) {
            const int idx = t + i * RT;
            if (idx < (NBINS + HPAD) / 4) h4[idx] = make_uint4(0, 0, 0, 0);
        }
    }
    #pragma unroll
    for (int i = 0; i < NPFX / RT; i++) lut[t + i * RT] = __ldg(&g_lut[t + i * RT]);

    // coalesced key loads (L2-hot: transpose ran just before)
    unsigned int myu[8];
    const unsigned int* xc = g_xT + (size_t)col * BATCH;
    #pragma unroll
    for (int k = 0; k < 8; k++) myu[k] = __ldg(&xc[t + k * RT]);
    __syncthreads();

    // single atomic pass: bin + within-bin sequence number, packed
    unsigned int packed[8];          // bin (14b) | off<<14
    #pragma unroll
    for (int k = 0; k < 8; k++) {
        const unsigned int u = myu[k];
        const unsigned int ent = lut[u >> 21];
        const unsigned int eb = ent & 15u;
        const unsigned int bin = (ent >> 4) + ((u >> (21 - eb)) & ((1u << eb) - 1u));
        const unsigned int off = atomicAdd(&hist[bin], 1u);
        packed[k] = bin | (off << 14);
    }
    __syncthreads();

    // exclusive scan: 32 warps x 320-bin chunks
    const int wbase = wid * (NBINS / 32);
    unsigned int carry = 0;
    #pragma unroll
    for (int r = 0; r < NBINS / 32 / 32; r++) {
        unsigned int v = hist[wbase + r * 32 + lane];
        unsigned int inc = v;
        #pragma unroll
        for (int d = 1; d < 32; d <<= 1) {
            unsigned int n = __shfl_up_sync(0xffffffffu, inc, d);
            if (lane >= d) inc += n;
        }
        hist[wbase + r * 32 + lane] = (inc - v) + carry;
        carry += __shfl_sync(0xffffffffu, inc, 31);
    }
    if (lane == 31) warpSums[wid] = carry;
    __syncthreads();
    if (wid == 0) {
        unsigned int orig = warpSums[lane];
        unsigned int inc = orig;
        #pragma unroll
        for (int d = 1; d < 32; d <<= 1) {
            unsigned int n = __shfl_up_sync(0xffffffffu, inc, d);
            if (lane >= d) inc += n;
        }
        warpSums[lane] = inc - orig;
    }
    __syncthreads();
    {
        const unsigned int add = warpSums[wid];
        if (add) {
            #pragma unroll
            for (int r = 0; r < NBINS / 32 / 32; r++)
                hist[wbase + r * 32 + lane] += add;
        }
    }
    if (t == 0) hist[NBINS] = BATCH;
    __syncthreads();

    // scatter via base + off (no atomics); hist stays exclusive-base
    #pragma unroll
    for (int k = 0; k < 8; k++) {
        const unsigned int bin = packed[k] & 16383u;
        const unsigned int off = packed[k] >> 14;
        const unsigned int pos = hist[bin] + off;
        S[pos] = myu[k];
        A[pos] = (unsigned short)(t + k * RT);
    }
    __syncthreads();

    // walk near-singleton bins; tie-index load only on key equality (rare)
    unsigned short* rc = g_rank16 + (size_t)col * BATCH;
    #pragma unroll
    for (int k = 0; k < 8; k++) {
        const int b = t + k * RT;
        const unsigned int u = myu[k];
        const unsigned int bin = packed[k] & 16383u;
        const unsigned int start = hist[bin];
        const unsigned int end = hist[bin + 1];
        unsigned int cnt = 0;
        for (unsigned int p = start; p < end; p++) {
            const unsigned int u2 = S[p];
            cnt += (u2 < u);
            if (u2 == u) cnt += ((int)A[p] < b);
        }
        rc[b] = (unsigned short)(start + cnt);   // coalesced u16 store
    }
}

// ---------------------------------------------------------------------------
// Kernel 3: transpose ranks back into out (coalesced both sides).
// ---------------------------------------------------------------------------
__global__ __launch_bounds__(256) void rank_out_kernel(float* __restrict__ out) {
    __shared__ unsigned int tile[64 * 33];   // [e][b/2] u16x2, pad 33
    const int b0 = blockIdx.x * 64;
    const int w = blockIdx.y;
    const int t = threadIdx.x;
    const int lane = t & 31;
    const int wr = t >> 5;                   // warp id 0..7

    #pragma unroll
    for (int i = 0; i < 8; i++) {
        const int e = wr * 8 + i;
        const unsigned int* src = (const unsigned int*)
            (g_rank16 + (size_t)(w * EF + e) * BATCH + b0);
        tile[e * 33 + lane] = src[lane];
    }
    __syncthreads();

    const float invB = 1.0f / BATCH;
    #pragma unroll
    for (int i = 0; i < 8; i++) {
        const int b = wr * 8 + i;
        float* o = out + (size_t)(b0 + b) * OUT_STRIDE + w * OUT_ROW + 2 * EF;
        #pragma unroll
        for (int h = 0; h < 2; h++) {
            const int e = h * 32 + lane;
            const unsigned int pk = tile[e * 33 + (b >> 1)];
            const unsigned int r = (b & 1) ? (pk >> 16) : (pk & 0xFFFFu);
            o[e] = (float)r * invB;
        }
    }
}

// ---------------------------------------------------------------------------
extern "C" void kernel_launch(void* const* d_in, const int* in_sizes, int n_in,
                              void* d_out, int out_size) {
    const float* x = (const float*)d_in[0];
    float* out = (float*)d_out;

    cudaFuncSetAttribute(rank_kernel, cudaFuncAttributeMaxDynamicSharedMemorySize,
                         DYN_SMEM);

    stats_kernel<<<BATCH, 256>>>(x, out);
    transpose_kernel<<<dim3(BATCH / 32, WWIN), 256>>>(x);
    lut_init_kernel<<<1, 1024>>>();
    rank_kernel<<<NCOLS, RT, DYN_SMEM>>>();
    rank_out_kernel<<<dim3(BATCH / 64, WWIN), 256>>>(out);
}